// round 6
// baseline (speedup 1.0000x reference)
#include <cuda_runtime.h>
#include <cuda_bf16.h>
#include <cstdint>

#define NUM_USERS 100000
#define NUM_ITEMS 200000
#define N_NODES   300000
#define NNZ       1200000

// Scratch (allocation-free rule: __device__ globals)
__device__ float g_emb[N_NODES * 64];               // carried (UN-normalized) embeddings
__device__ float g_side[N_NODES * 64];              // SpMM accumulator (kept zeroed between calls)
__device__ __nv_bfloat16 g_Bimg[3][2][64 * 128];    // [layer][hi/lo][n*128+k]

// ---------------------------------------------------------------------------
// helpers
// ---------------------------------------------------------------------------
__device__ __forceinline__ void mma_bf16(float* d, uint32_t a0, uint32_t a1,
                                         uint32_t a2, uint32_t a3,
                                         uint32_t b0, uint32_t b1) {
    asm volatile("mma.sync.aligned.m16n8k16.row.col.f32.bf16.bf16.f32 "
                 "{%0,%1,%2,%3}, {%4,%5,%6,%7}, {%8,%9}, {%0,%1,%2,%3};"
                 : "+f"(d[0]), "+f"(d[1]), "+f"(d[2]), "+f"(d[3])
                 : "r"(a0), "r"(a1), "r"(a2), "r"(a3), "r"(b0), "r"(b1));
}
__device__ __forceinline__ uint32_t pack_hi(float a, float b, float& ra, float& rb) {
    __nv_bfloat16 ha = __float2bfloat16_rn(a), hb = __float2bfloat16_rn(b);
    ra = a - __bfloat162float(ha);
    rb = b - __bfloat162float(hb);
    return (uint32_t)__bfloat16_as_ushort(ha) | ((uint32_t)__bfloat16_as_ushort(hb) << 16);
}
__device__ __forceinline__ uint32_t pack_lo(float a, float b) {
    __nv_bfloat16 ha = __float2bfloat16_rn(a), hb = __float2bfloat16_rn(b);
    return (uint32_t)__bfloat16_as_ushort(ha) | ((uint32_t)__bfloat16_as_ushort(hb) << 16);
}

// ---------------------------------------------------------------------------
// init: g_emb = concat(user_emb, item_emb); out[:, 0:64] = g_emb
// ---------------------------------------------------------------------------
__global__ __launch_bounds__(256) void k_init(const float* __restrict__ ue,
                                              const float* __restrict__ ie,
                                              float* __restrict__ out) {
    int idx = blockIdx.x * 256 + threadIdx.x;      // [0, N_NODES*16)
    if (idx >= N_NODES * 16) return;
    int node = idx >> 4, q = idx & 15;
    float4 v;
    if (node < NUM_USERS)
        v = ((const float4*)ue)[node * 16 + q];
    else
        v = ((const float4*)ie)[(node - NUM_USERS) * 16 + q];
    ((float4*)g_emb)[idx] = v;
    ((float4*)out)[node * 64 + q] = v;
}

// ---------------------------------------------------------------------------
// precompute B images: B[k][n] = k<64 ? Wc[l][k][n] : We[l][k-64][n]
// stored transposed [n][k], split hi/lo bf16
// ---------------------------------------------------------------------------
__global__ __launch_bounds__(256) void k_prepB(const float* __restrict__ Wc,
                                               const float* __restrict__ We) {
    int idx = blockIdx.x * 256 + threadIdx.x;      // 3 * 8192
    if (idx >= 3 * 8192) return;
    int l = idx >> 13, r = idx & 8191, n = r >> 7, k = r & 127;
    float w = (k < 64) ? Wc[l * 4096 + k * 64 + n] : We[l * 4096 + (k - 64) * 64 + n];
    __nv_bfloat16 h = __float2bfloat16_rn(w);
    __nv_bfloat16 lo = __float2bfloat16_rn(w - __bfloat162float(h));
    g_Bimg[l][0][n * 128 + k] = h;
    g_Bimg[l][1][n * 128 + k] = lo;
}

// ---------------------------------------------------------------------------
// SpMM: side[row] += val * emb[col]   (16 threads per edge, red.v4 atomics)
// ---------------------------------------------------------------------------
__global__ __launch_bounds__(256) void k_spmm(const int* __restrict__ rows,
                                              const int* __restrict__ cols,
                                              const float* __restrict__ vals) {
    int t = blockIdx.x * 256 + threadIdx.x;        // [0, NNZ*16)
    if (t >= NNZ * 16) return;
    int e = t >> 4, q = t & 15;
    int r = rows[e];
    int c = cols[e];
    float v = vals[e];
    float4 x = ((const float4*)g_emb)[(size_t)c * 16 + q];
    float* dst = g_side + (size_t)r * 64 + q * 4;
    asm volatile("red.global.add.v4.f32 [%0], {%1,%2,%3,%4};"
                 :: "l"(dst), "f"(x.x * v), "f"(x.y * v), "f"(x.z * v), "f"(x.w * v)
                 : "memory");
}

// ---------------------------------------------------------------------------
// HMMA fused layer: D = [side | side*emb] @ [Wc;We] via 3-term bf16 split,
// epilogue bias + leaky(0.2) + (emb <- act, out <- act/||act||), side zeroed.
// 256 threads (8 warps), 128-row tile, mma.sync m16n8k16 bf16.
// smem rows padded to 272B (17x16B) => conflict-free b32 fragment loads.
// ---------------------------------------------------------------------------
#define PITCH 272                          // bytes per smem row (136 bf16)
#define SB0   0                            // 64 rows  -> 17408 B
#define SB1   17408
#define SA0   34816                        // 128 rows -> 34816 B
#define SA1   69632
#define SBIAS 104448
#define GEMM_SMEM 104704

__global__ __launch_bounds__(256) void k_gemm(const float* __restrict__ bc,
                                              const float* __restrict__ be,
                                              float* __restrict__ out, int layer) {
    extern __shared__ char smem[];
    const int tid = threadIdx.x, wid = tid >> 5, lane = tid & 31;
    const int base = blockIdx.x * 128;
    float* sBias = (float*)(smem + SBIAS);

    // --- B operand: straight copy of precomputed hi/lo images, padded rows ---
    {
        const float4* bs = (const float4*)&g_Bimg[layer][0][0];   // 2048 float4 (hi then lo)
        #pragma unroll
        for (int it = 0; it < 8; ++it) {
            int i = it * 256 + tid;                // [0,2048)
            int img = i >> 10, r2 = i & 1023;
            int n = r2 >> 4, c = r2 & 15;
            *(float4*)(smem + (img ? SB1 : SB0) + n * PITCH + c * 16) = bs[i];
        }
    }
    if (tid < 64) sBias[tid] = bc[layer * 64 + tid] + be[layer * 64 + tid];

    // --- A operand: load side/emb, zero side, hi/lo split, padded stores ---
    {
        #pragma unroll
        for (int it = 0; it < 8; ++it) {
            int i = it * 256 + tid;                // [0,2048): 128 rows x 16 q
            int row = i >> 4, q = i & 15;
            int gn = base + row;
            float4 s = make_float4(0.f, 0.f, 0.f, 0.f);
            float4 e = make_float4(0.f, 0.f, 0.f, 0.f);
            if (gn < N_NODES) {
                s = ((const float4*)g_side)[(size_t)gn * 16 + q];
                e = ((const float4*)g_emb)[(size_t)gn * 16 + q];
                ((float4*)g_side)[(size_t)gn * 16 + q] = make_float4(0.f, 0.f, 0.f, 0.f);
            }
            float4 p = make_float4(s.x * e.x, s.y * e.y, s.z * e.z, s.w * e.w);
            float rx, ry, rz, rw;
            uint32_t h0, h1;
            // side -> k = 4q
            h0 = pack_hi(s.x, s.y, rx, ry);
            h1 = pack_hi(s.z, s.w, rz, rw);
            *(uint2*)(smem + SA0 + row * PITCH + q * 8) = make_uint2(h0, h1);
            *(uint2*)(smem + SA1 + row * PITCH + q * 8) =
                make_uint2(pack_lo(rx, ry), pack_lo(rz, rw));
            // side*emb -> k = 64 + 4q
            h0 = pack_hi(p.x, p.y, rx, ry);
            h1 = pack_hi(p.z, p.w, rz, rw);
            *(uint2*)(smem + SA0 + row * PITCH + 128 + q * 8) = make_uint2(h0, h1);
            *(uint2*)(smem + SA1 + row * PITCH + 128 + q * 8) =
                make_uint2(pack_lo(rx, ry), pack_lo(rz, rw));
        }
    }
    __syncthreads();

    // --- MMA mainloop: warp wid owns rows 16*wid..+15, all 64 cols ---
    const int r = lane >> 2, c4 = lane & 3;
    float acc[8][4];
    #pragma unroll
    for (int nt = 0; nt < 8; ++nt)
        #pragma unroll
        for (int i = 0; i < 4; ++i) acc[nt][i] = 0.f;

    const char* pa0 = smem + SA0 + (16 * wid + r) * PITCH + c4 * 4;
    const char* pa1 = smem + SA1 + (16 * wid + r) * PITCH + c4 * 4;
    const char* pb0 = smem + SB0 + r * PITCH + c4 * 4;
    const char* pb1 = smem + SB1 + r * PITCH + c4 * 4;

    #pragma unroll
    for (int ks = 0; ks < 8; ++ks) {
        const int kb = ks * 32;                    // 16 k * 2B
        uint32_t a0 = *(const uint32_t*)(pa0 + kb);
        uint32_t a1 = *(const uint32_t*)(pa0 + kb + 8 * PITCH);
        uint32_t a2 = *(const uint32_t*)(pa0 + kb + 16);
        uint32_t a3 = *(const uint32_t*)(pa0 + kb + 8 * PITCH + 16);
        uint32_t l0 = *(const uint32_t*)(pa1 + kb);
        uint32_t l1 = *(const uint32_t*)(pa1 + kb + 8 * PITCH);
        uint32_t l2 = *(const uint32_t*)(pa1 + kb + 16);
        uint32_t l3 = *(const uint32_t*)(pa1 + kb + 8 * PITCH + 16);
        #pragma unroll
        for (int nt = 0; nt < 8; ++nt) {
            uint32_t bh0 = *(const uint32_t*)(pb0 + nt * 8 * PITCH + kb);
            uint32_t bh1 = *(const uint32_t*)(pb0 + nt * 8 * PITCH + kb + 16);
            uint32_t bl0 = *(const uint32_t*)(pb1 + nt * 8 * PITCH + kb);
            uint32_t bl1 = *(const uint32_t*)(pb1 + nt * 8 * PITCH + kb + 16);
            mma_bf16(acc[nt], a0, a1, a2, a3, bh0, bh1);   // a_hi * b_hi
            mma_bf16(acc[nt], l0, l1, l2, l3, bh0, bh1);   // a_lo * b_hi
            mma_bf16(acc[nt], a0, a1, a2, a3, bl0, bl1);   // a_hi * b_lo
        }
    }

    // --- epilogue: bias + leaky + row-L2; rows R0 = base+16w+r, R1 = R0+8 ---
    float ssq0 = 0.f, ssq1 = 0.f;
    #pragma unroll
    for (int nt = 0; nt < 8; ++nt) {
        float2 bv = *(float2*)(sBias + nt * 8 + 2 * c4);
        float x0 = acc[nt][0] + bv.x, x1 = acc[nt][1] + bv.y;
        float y0 = acc[nt][2] + bv.x, y1 = acc[nt][3] + bv.y;
        x0 = (x0 > 0.f) ? x0 : 0.2f * x0;
        x1 = (x1 > 0.f) ? x1 : 0.2f * x1;
        y0 = (y0 > 0.f) ? y0 : 0.2f * y0;
        y1 = (y1 > 0.f) ? y1 : 0.2f * y1;
        acc[nt][0] = x0; acc[nt][1] = x1; acc[nt][2] = y0; acc[nt][3] = y1;
        ssq0 += x0 * x0 + x1 * x1;
        ssq1 += y0 * y0 + y1 * y1;
    }
    // reduce across the 4 lanes of the quad (same row)
    ssq0 += __shfl_xor_sync(0xffffffffu, ssq0, 1);
    ssq0 += __shfl_xor_sync(0xffffffffu, ssq0, 2);
    ssq1 += __shfl_xor_sync(0xffffffffu, ssq1, 1);
    ssq1 += __shfl_xor_sync(0xffffffffu, ssq1, 2);
    float sc0 = (ssq0 > 0.f) ? rsqrtf(ssq0) : 0.f;
    float sc1 = (ssq1 > 0.f) ? rsqrtf(ssq1) : 0.f;

    const int R0 = base + 16 * wid + r;
    const int R1 = R0 + 8;
    const int outc = (layer + 1) * 64;
    if (R0 < N_NODES) {
        #pragma unroll
        for (int nt = 0; nt < 8; ++nt) {
            int col = nt * 8 + 2 * c4;
            *(float2*)(g_emb + (size_t)R0 * 64 + col) = make_float2(acc[nt][0], acc[nt][1]);
            *(float2*)(out + (size_t)R0 * 256 + outc + col) =
                make_float2(acc[nt][0] * sc0, acc[nt][1] * sc0);
        }
    }
    if (R1 < N_NODES) {
        #pragma unroll
        for (int nt = 0; nt < 8; ++nt) {
            int col = nt * 8 + 2 * c4;
            *(float2*)(g_emb + (size_t)R1 * 64 + col) = make_float2(acc[nt][2], acc[nt][3]);
            *(float2*)(out + (size_t)R1 * 256 + outc + col) =
                make_float2(acc[nt][2] * sc1, acc[nt][3] * sc1);
        }
    }
}

// ---------------------------------------------------------------------------
// launch
// ---------------------------------------------------------------------------
extern "C" void kernel_launch(void* const* d_in, const int* in_sizes, int n_in,
                              void* d_out, int out_size) {
    const int*   rows = (const int*)d_in[0];
    const int*   cols = (const int*)d_in[1];
    const float* vals = (const float*)d_in[2];
    const float* ue   = (const float*)d_in[3];
    const float* ie   = (const float*)d_in[4];
    const float* Wc   = (const float*)d_in[5];
    const float* bc   = (const float*)d_in[6];
    const float* We   = (const float*)d_in[7];
    const float* be   = (const float*)d_in[8];
    float* out = (float*)d_out;

    cudaFuncSetAttribute(k_gemm, cudaFuncAttributeMaxDynamicSharedMemorySize, GEMM_SMEM);

    const int n_elem4 = N_NODES * 16;                 // 4.8M float4
    k_init<<<(n_elem4 + 255) / 256, 256>>>(ue, ie, out);
    k_prepB<<<96, 256>>>(Wc, We);

    const int spmm_threads = NNZ * 16;                // 19.2M
    const int gemm_blocks  = (N_NODES + 127) / 128;   // 2344

    for (int l = 0; l < 3; ++l) {
        // g_side is zero here: statically on first call, then re-zeroed by the
        // previous layer's / previous call's k_gemm as it consumes it.
        k_spmm<<<(spmm_threads + 255) / 256, 256>>>(rows, cols, vals);
        k_gemm<<<gemm_blocks, 256, GEMM_SMEM>>>(bc, be, out, l);
    }
}

// round 9
// speedup vs baseline: 1.6731x; 1.6731x over previous
#include <cuda_runtime.h>
#include <cuda_bf16.h>
#include <cstdint>

#define NUM_USERS 100000
#define NUM_ITEMS 200000
#define N_NODES   300000
#define NNZ       1200000

// Scratch (allocation-free rule: __device__ globals)
__device__ float g_emb[N_NODES * 64];               // carried (UN-normalized) embeddings
__device__ float g_side[N_NODES * 64];              // SpMM accumulator (kept zeroed between calls)
__device__ __nv_bfloat16 g_Bimg[3][2][64 * 128];    // [layer][hi/lo][n*128+k]

// ---------------------------------------------------------------------------
// helpers
// ---------------------------------------------------------------------------
__device__ __forceinline__ void mma_bf16(float* d, uint32_t a0, uint32_t a1,
                                         uint32_t a2, uint32_t a3,
                                         uint32_t b0, uint32_t b1) {
    asm volatile("mma.sync.aligned.m16n8k16.row.col.f32.bf16.bf16.f32 "
                 "{%0,%1,%2,%3}, {%4,%5,%6,%7}, {%8,%9}, {%0,%1,%2,%3};"
                 : "+f"(d[0]), "+f"(d[1]), "+f"(d[2]), "+f"(d[3])
                 : "r"(a0), "r"(a1), "r"(a2), "r"(a3), "r"(b0), "r"(b1));
}
__device__ __forceinline__ uint32_t pack_hi(float a, float b, float& ra, float& rb) {
    __nv_bfloat16 ha = __float2bfloat16_rn(a), hb = __float2bfloat16_rn(b);
    ra = a - __bfloat162float(ha);
    rb = b - __bfloat162float(hb);
    return (uint32_t)__bfloat16_as_ushort(ha) | ((uint32_t)__bfloat16_as_ushort(hb) << 16);
}
__device__ __forceinline__ uint32_t pack_lo(float a, float b) {
    __nv_bfloat16 ha = __float2bfloat16_rn(a), hb = __float2bfloat16_rn(b);
    return (uint32_t)__bfloat16_as_ushort(ha) | ((uint32_t)__bfloat16_as_ushort(hb) << 16);
}
__device__ __forceinline__ float2 ldf2z(const float* p, bool v) {
    return v ? *(const float2*)p : make_float2(0.f, 0.f);
}

// ---------------------------------------------------------------------------
// init: g_emb = concat(user_emb, item_emb); out[:, 0:64] = g_emb
// ---------------------------------------------------------------------------
__global__ __launch_bounds__(256) void k_init(const float* __restrict__ ue,
                                              const float* __restrict__ ie,
                                              float* __restrict__ out) {
    int idx = blockIdx.x * 256 + threadIdx.x;      // [0, N_NODES*16)
    if (idx >= N_NODES * 16) return;
    int node = idx >> 4, q = idx & 15;
    float4 v;
    if (node < NUM_USERS)
        v = ((const float4*)ue)[node * 16 + q];
    else
        v = ((const float4*)ie)[(node - NUM_USERS) * 16 + q];
    ((float4*)g_emb)[idx] = v;
    ((float4*)out)[node * 64 + q] = v;
}

// ---------------------------------------------------------------------------
// precompute B images: B[k][n] = k<64 ? Wc[l][k][n] : We[l][k-64][n]
// stored transposed [n][k], split hi/lo bf16
// ---------------------------------------------------------------------------
__global__ __launch_bounds__(256) void k_prepB(const float* __restrict__ Wc,
                                               const float* __restrict__ We) {
    int idx = blockIdx.x * 256 + threadIdx.x;      // 3 * 8192
    if (idx >= 3 * 8192) return;
    int l = idx >> 13, r = idx & 8191, n = r >> 7, k = r & 127;
    float w = (k < 64) ? Wc[l * 4096 + k * 64 + n] : We[l * 4096 + (k - 64) * 64 + n];
    __nv_bfloat16 h = __float2bfloat16_rn(w);
    __nv_bfloat16 lo = __float2bfloat16_rn(w - __bfloat162float(h));
    g_Bimg[l][0][n * 128 + k] = h;
    g_Bimg[l][1][n * 128 + k] = lo;
}

// ---------------------------------------------------------------------------
// SpMM: side[row] += val * emb[col]   (16 threads per edge, red.v4 atomics)
// ---------------------------------------------------------------------------
__global__ __launch_bounds__(256) void k_spmm(const int* __restrict__ rows,
                                              const int* __restrict__ cols,
                                              const float* __restrict__ vals) {
    int t = blockIdx.x * 256 + threadIdx.x;        // [0, NNZ*16)
    if (t >= NNZ * 16) return;
    int e = t >> 4, q = t & 15;
    int r = rows[e];
    int c = cols[e];
    float v = vals[e];
    float4 x = ((const float4*)g_emb)[(size_t)c * 16 + q];
    float* dst = g_side + (size_t)r * 64 + q * 4;
    asm volatile("red.global.add.v4.f32 [%0], {%1,%2,%3,%4};"
                 :: "l"(dst), "f"(x.x * v), "f"(x.y * v), "f"(x.z * v), "f"(x.w * v)
                 : "memory");
}

// ---------------------------------------------------------------------------
// HMMA fused layer, register-direct A path:
//   A fragments loaded straight from g_side/g_emb (coalesced float2),
//   packed to bf16 hi/lo in registers. Only B lives in smem (35 KB/CTA).
//   D = [side | side*emb] @ [Wc;We] via 3-term bf16 split.
//   Epilogue: bias + leaky(0.2); g_emb <- act; out <- act/||act||; side zeroed.
// 256 threads (8 warps), 128-row tile, mma.sync m16n8k16 bf16.
// ---------------------------------------------------------------------------
#define PITCH 272                          // bytes per smem B row (136 bf16)
#define SB0   0                            // 64 rows -> 17408 B
#define SB1   17408
#define SBIAS 34816
#define GEMM_SMEM 35072

__global__ __launch_bounds__(256) void k_gemm(const float* __restrict__ bc,
                                              const float* __restrict__ be,
                                              float* __restrict__ out, int layer) {
    extern __shared__ char smem[];
    const int tid = threadIdx.x, wid = tid >> 5, lane = tid & 31;
    const int base = blockIdx.x * 128;
    float* sBias = (float*)(smem + SBIAS);

    // --- B operand: straight copy of precomputed hi/lo images, padded rows ---
    {
        const float4* bs = (const float4*)&g_Bimg[layer][0][0];   // 2048 float4 (hi then lo)
        #pragma unroll
        for (int it = 0; it < 8; ++it) {
            int i = it * 256 + tid;                // [0,2048)
            int img = i >> 10, r2 = i & 1023;
            int n = r2 >> 4, c = r2 & 15;
            *(float4*)(smem + (img ? SB1 : SB0) + n * PITCH + c * 16) = bs[i];
        }
    }
    if (tid < 64) sBias[tid] = bc[layer * 64 + tid] + be[layer * 64 + tid];
    __syncthreads();

    // --- mainloop: A fragments direct from global, B fragments from smem ---
    const int r = lane >> 2, c4 = lane & 3;
    const int R0 = base + 16 * wid + r;
    const int R1 = R0 + 8;
    const bool v0 = R0 < N_NODES, v1 = R1 < N_NODES;
    float* s0p = g_side + (size_t)R0 * 64;
    float* s1p = g_side + (size_t)R1 * 64;
    const float* e0p = g_emb + (size_t)R0 * 64;
    const float* e1p = g_emb + (size_t)R1 * 64;
    const int kA = 2 * c4, kB = 8 + 2 * c4;

    const char* pb0 = smem + SB0 + r * PITCH + c4 * 4;
    const char* pb1 = smem + SB1 + r * PITCH + c4 * 4;

    float acc[8][4];
    #pragma unroll
    for (int nt = 0; nt < 8; ++nt)
        #pragma unroll
        for (int i = 0; i < 4; ++i) acc[nt][i] = 0.f;

    #pragma unroll
    for (int ks = 0; ks < 8; ++ks) {
        float2 v00, v01, v10, v11;
        if (ks < 4) {
            const int k0 = ks * 16 + kA, k1 = ks * 16 + kB;
            v00 = ldf2z(s0p + k0, v0);
            v01 = ldf2z(s0p + k1, v0);
            v10 = ldf2z(s1p + k0, v1);
            v11 = ldf2z(s1p + k1, v1);
        } else {
            const int k0 = (ks - 4) * 16 + kA, k1 = (ks - 4) * 16 + kB;
            float2 s00 = ldf2z(s0p + k0, v0), s01 = ldf2z(s0p + k1, v0);
            float2 s10 = ldf2z(s1p + k0, v1), s11 = ldf2z(s1p + k1, v1);
            float2 e00 = ldf2z(e0p + k0, v0), e01 = ldf2z(e0p + k1, v0);
            float2 e10 = ldf2z(e1p + k0, v1), e11 = ldf2z(e1p + k1, v1);
            // final read of these side slots -> zero them (fused k_zero)
            const float2 z2 = make_float2(0.f, 0.f);
            if (v0) { *(float2*)(s0p + k0) = z2; *(float2*)(s0p + k1) = z2; }
            if (v1) { *(float2*)(s1p + k0) = z2; *(float2*)(s1p + k1) = z2; }
            v00 = make_float2(s00.x * e00.x, s00.y * e00.y);
            v01 = make_float2(s01.x * e01.x, s01.y * e01.y);
            v10 = make_float2(s10.x * e10.x, s10.y * e10.y);
            v11 = make_float2(s11.x * e11.x, s11.y * e11.y);
        }
        // pack A fragments: a0=(R0,k), a1=(R1,k), a2=(R0,k+8), a3=(R1,k+8)
        float l00x, l00y, l01x, l01y, l10x, l10y, l11x, l11y;
        uint32_t a0 = pack_hi(v00.x, v00.y, l00x, l00y);
        uint32_t a1 = pack_hi(v10.x, v10.y, l10x, l10y);
        uint32_t a2 = pack_hi(v01.x, v01.y, l01x, l01y);
        uint32_t a3 = pack_hi(v11.x, v11.y, l11x, l11y);
        uint32_t q0 = pack_lo(l00x, l00y);
        uint32_t q1 = pack_lo(l10x, l10y);
        uint32_t q2 = pack_lo(l01x, l01y);
        uint32_t q3 = pack_lo(l11x, l11y);

        const int kb = ks * 32;                    // byte offset in B row
        #pragma unroll
        for (int nt = 0; nt < 8; ++nt) {
            uint32_t bh0 = *(const uint32_t*)(pb0 + nt * 8 * PITCH + kb);
            uint32_t bh1 = *(const uint32_t*)(pb0 + nt * 8 * PITCH + kb + 16);
            uint32_t bl0 = *(const uint32_t*)(pb1 + nt * 8 * PITCH + kb);
            uint32_t bl1 = *(const uint32_t*)(pb1 + nt * 8 * PITCH + kb + 16);
            mma_bf16(acc[nt], a0, a1, a2, a3, bh0, bh1);   // a_hi * b_hi
            mma_bf16(acc[nt], q0, q1, q2, q3, bh0, bh1);   // a_lo * b_hi
            mma_bf16(acc[nt], a0, a1, a2, a3, bl0, bl1);   // a_hi * b_lo
        }
    }

    // --- epilogue: bias + leaky + row-L2; rows R0 and R1 ---
    float ssq0 = 0.f, ssq1 = 0.f;
    #pragma unroll
    for (int nt = 0; nt < 8; ++nt) {
        float2 bv = *(float2*)(sBias + nt * 8 + 2 * c4);
        float x0 = acc[nt][0] + bv.x, x1 = acc[nt][1] + bv.y;
        float y0 = acc[nt][2] + bv.x, y1 = acc[nt][3] + bv.y;
        x0 = (x0 > 0.f) ? x0 : 0.2f * x0;
        x1 = (x1 > 0.f) ? x1 : 0.2f * x1;
        y0 = (y0 > 0.f) ? y0 : 0.2f * y0;
        y1 = (y1 > 0.f) ? y1 : 0.2f * y1;
        acc[nt][0] = x0; acc[nt][1] = x1; acc[nt][2] = y0; acc[nt][3] = y1;
        ssq0 += x0 * x0 + x1 * x1;
        ssq1 += y0 * y0 + y1 * y1;
    }
    // reduce across the 4 lanes of the quad (same row)
    ssq0 += __shfl_xor_sync(0xffffffffu, ssq0, 1);
    ssq0 += __shfl_xor_sync(0xffffffffu, ssq0, 2);
    ssq1 += __shfl_xor_sync(0xffffffffu, ssq1, 1);
    ssq1 += __shfl_xor_sync(0xffffffffu, ssq1, 2);
    float sc0 = (ssq0 > 0.f) ? rsqrtf(ssq0) : 0.f;
    float sc1 = (ssq1 > 0.f) ? rsqrtf(ssq1) : 0.f;

    const int outc = (layer + 1) * 64;
    if (v0) {
        #pragma unroll
        for (int nt = 0; nt < 8; ++nt) {
            int col = nt * 8 + 2 * c4;
            *(float2*)(g_emb + (size_t)R0 * 64 + col) = make_float2(acc[nt][0], acc[nt][1]);
            *(float2*)(out + (size_t)R0 * 256 + outc + col) =
                make_float2(acc[nt][0] * sc0, acc[nt][1] * sc0);
        }
    }
    if (v1) {
        #pragma unroll
        for (int nt = 0; nt < 8; ++nt) {
            int col = nt * 8 + 2 * c4;
            *(float2*)(g_emb + (size_t)R1 * 64 + col) = make_float2(acc[nt][2], acc[nt][3]);
            *(float2*)(out + (size_t)R1 * 256 + outc + col) =
                make_float2(acc[nt][2] * sc1, acc[nt][3] * sc1);
        }
    }
}

// ---------------------------------------------------------------------------
// launch
// ---------------------------------------------------------------------------
extern "C" void kernel_launch(void* const* d_in, const int* in_sizes, int n_in,
                              void* d_out, int out_size) {
    const int*   rows = (const int*)d_in[0];
    const int*   cols = (const int*)d_in[1];
    const float* vals = (const float*)d_in[2];
    const float* ue   = (const float*)d_in[3];
    const float* ie   = (const float*)d_in[4];
    const float* Wc   = (const float*)d_in[5];
    const float* bc   = (const float*)d_in[6];
    const float* We   = (const float*)d_in[7];
    const float* be   = (const float*)d_in[8];
    float* out = (float*)d_out;

    cudaFuncSetAttribute(k_gemm, cudaFuncAttributeMaxDynamicSharedMemorySize, GEMM_SMEM);

    const int n_elem4 = N_NODES * 16;                 // 4.8M float4
    k_init<<<(n_elem4 + 255) / 256, 256>>>(ue, ie, out);
    k_prepB<<<96, 256>>>(Wc, We);

    const int spmm_threads = NNZ * 16;                // 19.2M
    const int gemm_blocks  = (N_NODES + 127) / 128;   // 2344

    for (int l = 0; l < 3; ++l) {
        // g_side is zero here: statically on first call, then re-zeroed by the
        // previous layer's / previous call's k_gemm as it consumes it.
        k_spmm<<<(spmm_threads + 255) / 256, 256>>>(rows, cols, vals);
        k_gemm<<<gemm_blocks, 256, GEMM_SMEM>>>(bc, be, out, l);
    }
}

// round 13
// speedup vs baseline: 1.9255x; 1.1509x over previous
#include <cuda_runtime.h>
#include <cuda_bf16.h>
#include <cstdint>

#define NUM_USERS 100000
#define NUM_ITEMS 200000
#define N_NODES   300000
#define NNZ       1200000
#define NB_SCAN   293                      // ceil(300000/1024)

// Scratch (allocation-free rule: __device__ globals)
__device__ float g_emb[N_NODES * 64];               // carried (UN-normalized) embeddings
__device__ float g_side[N_NODES * 64];              // SpMM output (fully overwritten per layer)
__device__ __nv_bfloat16 g_Bimg[3][2][64 * 128];    // [layer][hi/lo][n*128+k]
__device__ int  g_cnt[N_NODES];                     // histogram
__device__ int  g_rowptr[N_NODES + 1];              // CSR row pointers
__device__ int  g_cur[N_NODES];                     // scatter cursors
__device__ int  g_blksum[NB_SCAN];                  // scan block sums
__device__ int2 g_edge[NNZ];                        // CSR edges: {col, val_bits}

// ---------------------------------------------------------------------------
// helpers
// ---------------------------------------------------------------------------
__device__ __forceinline__ void mma_bf16(float* d, uint32_t a0, uint32_t a1,
                                         uint32_t a2, uint32_t a3,
                                         uint32_t b0, uint32_t b1) {
    asm volatile("mma.sync.aligned.m16n8k16.row.col.f32.bf16.bf16.f32 "
                 "{%0,%1,%2,%3}, {%4,%5,%6,%7}, {%8,%9}, {%0,%1,%2,%3};"
                 : "+f"(d[0]), "+f"(d[1]), "+f"(d[2]), "+f"(d[3])
                 : "r"(a0), "r"(a1), "r"(a2), "r"(a3), "r"(b0), "r"(b1));
}
__device__ __forceinline__ uint32_t pack_hi(float a, float b, float& ra, float& rb) {
    __nv_bfloat16 ha = __float2bfloat16_rn(a), hb = __float2bfloat16_rn(b);
    ra = a - __bfloat162float(ha);
    rb = b - __bfloat162float(hb);
    return (uint32_t)__bfloat16_as_ushort(ha) | ((uint32_t)__bfloat16_as_ushort(hb) << 16);
}
__device__ __forceinline__ uint32_t pack_lo(float a, float b) {
    __nv_bfloat16 ha = __float2bfloat16_rn(a), hb = __float2bfloat16_rn(b);
    return (uint32_t)__bfloat16_as_ushort(ha) | ((uint32_t)__bfloat16_as_ushort(hb) << 16);
}
__device__ __forceinline__ float2 ldf2z(const float* p, bool v) {
    return v ? *(const float2*)p : make_float2(0.f, 0.f);
}

// ---------------------------------------------------------------------------
// init: g_emb = concat(user_emb, item_emb); out[:, 0:64] = g_emb
// ---------------------------------------------------------------------------
__global__ __launch_bounds__(256) void k_init(const float* __restrict__ ue,
                                              const float* __restrict__ ie,
                                              float* __restrict__ out) {
    int idx = blockIdx.x * 256 + threadIdx.x;      // [0, N_NODES*16)
    if (idx >= N_NODES * 16) return;
    int node = idx >> 4, q = idx & 15;
    float4 v;
    if (node < NUM_USERS)
        v = ((const float4*)ue)[node * 16 + q];
    else
        v = ((const float4*)ie)[(node - NUM_USERS) * 16 + q];
    ((float4*)g_emb)[idx] = v;
    ((float4*)out)[node * 64 + q] = v;
}

// ---------------------------------------------------------------------------
// precompute B images: B[k][n] = k<64 ? Wc[l][k][n] : We[l][k-64][n]
// stored transposed [n][k], split hi/lo bf16
// ---------------------------------------------------------------------------
__global__ __launch_bounds__(256) void k_prepB(const float* __restrict__ Wc,
                                               const float* __restrict__ We) {
    int idx = blockIdx.x * 256 + threadIdx.x;      // 3 * 8192
    if (idx >= 3 * 8192) return;
    int l = idx >> 13, r = idx & 8191, n = r >> 7, k = r & 127;
    float w = (k < 64) ? Wc[l * 4096 + k * 64 + n] : We[l * 4096 + (k - 64) * 64 + n];
    __nv_bfloat16 h = __float2bfloat16_rn(w);
    __nv_bfloat16 lo = __float2bfloat16_rn(w - __bfloat162float(h));
    g_Bimg[l][0][n * 128 + k] = h;
    g_Bimg[l][1][n * 128 + k] = lo;
}

// ---------------------------------------------------------------------------
// CSR build: histogram -> block scan -> scatter
// ---------------------------------------------------------------------------
__global__ __launch_bounds__(1024) void k_zcnt() {
    int i = blockIdx.x * 1024 + threadIdx.x;
    if (i < N_NODES) g_cnt[i] = 0;
}
__global__ __launch_bounds__(256) void k_hist(const int* __restrict__ rows) {
    int e = blockIdx.x * 256 + threadIdx.x;
    if (e < NNZ) atomicAdd(&g_cnt[rows[e]], 1);
}
__global__ __launch_bounds__(1024) void k_scan1() {
    __shared__ int sm[1024];
    const int t = threadIdx.x, b = blockIdx.x;
    const int i = b * 1024 + t;
    int v = (i < N_NODES) ? g_cnt[i] : 0;
    sm[t] = v;
    __syncthreads();
    #pragma unroll
    for (int off = 1; off < 1024; off <<= 1) {
        int x = (t >= off) ? sm[t - off] : 0;
        __syncthreads();
        sm[t] += x;
        __syncthreads();
    }
    if (i < N_NODES) g_rowptr[i] = sm[t] - v;      // exclusive within block
    if (t == 1023) g_blksum[b] = sm[1023];
}
__global__ __launch_bounds__(512) void k_scan2() {
    __shared__ int sm[512];
    const int t = threadIdx.x;
    int v = (t < NB_SCAN) ? g_blksum[t] : 0;
    sm[t] = v;
    __syncthreads();
    #pragma unroll
    for (int off = 1; off < 512; off <<= 1) {
        int x = (t >= off) ? sm[t - off] : 0;
        __syncthreads();
        sm[t] += x;
        __syncthreads();
    }
    if (t < NB_SCAN) g_blksum[t] = sm[t] - v;      // exclusive across blocks
    if (t == 0) g_rowptr[N_NODES] = NNZ;
}
__global__ __launch_bounds__(1024) void k_scan3() {
    int i = blockIdx.x * 1024 + threadIdx.x;
    if (i < N_NODES) {
        int rp = g_rowptr[i] + g_blksum[blockIdx.x];
        g_rowptr[i] = rp;
        g_cur[i] = rp;
    }
}
__global__ __launch_bounds__(256) void k_scatter(const int* __restrict__ rows,
                                                 const int* __restrict__ cols,
                                                 const float* __restrict__ vals) {
    int e = blockIdx.x * 256 + threadIdx.x;
    if (e >= NNZ) return;
    int pos = atomicAdd(&g_cur[rows[e]], 1);
    g_edge[pos] = make_int2(cols[e], __float_as_int(vals[e]));
}

// ---------------------------------------------------------------------------
// CSR SpMM: side[row] = sum_e val * emb[col].  Half-warp (16 lanes) per row,
// lane owns one float4 chunk; plain store, no atomics, full overwrite.
// ---------------------------------------------------------------------------
__global__ __launch_bounds__(256) void k_spmm2() {
    const int tid = threadIdx.x, wid = tid >> 5, lane = tid & 31;
    const int half = lane >> 4, q = lane & 15;
    const int row = blockIdx.x * 16 + wid * 2 + half;
    if (row >= N_NODES) return;
    const int s = g_rowptr[row], e = g_rowptr[row + 1];
    float4 acc = make_float4(0.f, 0.f, 0.f, 0.f);
    const float4* emb4 = (const float4*)g_emb;
    for (int i = s; i < e; ++i) {
        int2 ed = g_edge[i];
        float v = __int_as_float(ed.y);
        float4 x = emb4[(size_t)ed.x * 16 + q];
        acc.x += v * x.x;
        acc.y += v * x.y;
        acc.z += v * x.z;
        acc.w += v * x.w;
    }
    ((float4*)g_side)[(size_t)row * 16 + q] = acc;
}

// ---------------------------------------------------------------------------
// HMMA fused layer, register-direct A, paired k-steps:
//   for kp in 0..3: load side+emb once; MMA set for A=side (k-step kp) and
//   A=side*emb (k-step kp+4). 3-term bf16 split. No side writes.
//   Epilogue: bias + leaky(0.2); g_emb <- act; out <- act/||act||.
// ---------------------------------------------------------------------------
#define PITCH 272                          // bytes per smem B row (136 bf16)
#define SB0   0                            // 64 rows -> 17408 B
#define SB1   17408
#define SBIAS 34816
#define GEMM_SMEM 35072

__global__ __launch_bounds__(256) void k_gemm(const float* __restrict__ bc,
                                              const float* __restrict__ be,
                                              float* __restrict__ out, int layer) {
    extern __shared__ char smem[];
    const int tid = threadIdx.x, wid = tid >> 5, lane = tid & 31;
    const int base = blockIdx.x * 128;
    float* sBias = (float*)(smem + SBIAS);

    // --- B operand: straight copy of precomputed hi/lo images, padded rows ---
    {
        const float4* bs = (const float4*)&g_Bimg[layer][0][0];   // 2048 float4 (hi then lo)
        #pragma unroll
        for (int it = 0; it < 8; ++it) {
            int i = it * 256 + tid;                // [0,2048)
            int img = i >> 10, r2 = i & 1023;
            int n = r2 >> 4, c = r2 & 15;
            *(float4*)(smem + (img ? SB1 : SB0) + n * PITCH + c * 16) = bs[i];
        }
    }
    if (tid < 64) sBias[tid] = bc[layer * 64 + tid] + be[layer * 64 + tid];
    __syncthreads();

    // --- mainloop: A fragments direct from global, B fragments from smem ---
    const int r = lane >> 2, c4 = lane & 3;
    const int R0 = base + 16 * wid + r;
    const int R1 = R0 + 8;
    const bool v0 = R0 < N_NODES, v1 = R1 < N_NODES;
    const float* s0p = g_side + (size_t)R0 * 64;
    const float* s1p = g_side + (size_t)R1 * 64;
    const float* e0p = g_emb + (size_t)R0 * 64;
    const float* e1p = g_emb + (size_t)R1 * 64;
    const int kA = 2 * c4, kB = 8 + 2 * c4;

    const char* pb0 = smem + SB0 + r * PITCH + c4 * 4;
    const char* pb1 = smem + SB1 + r * PITCH + c4 * 4;

    float acc[8][4];
    #pragma unroll
    for (int nt = 0; nt < 8; ++nt)
        #pragma unroll
        for (int i = 0; i < 4; ++i) acc[nt][i] = 0.f;

    #pragma unroll
    for (int kp = 0; kp < 4; ++kp) {
        const int k0 = kp * 16 + kA, k1 = kp * 16 + kB;
        float2 s00 = ldf2z(s0p + k0, v0), s01 = ldf2z(s0p + k1, v0);
        float2 s10 = ldf2z(s1p + k0, v1), s11 = ldf2z(s1p + k1, v1);
        float2 e00 = ldf2z(e0p + k0, v0), e01 = ldf2z(e0p + k1, v0);
        float2 e10 = ldf2z(e1p + k0, v1), e11 = ldf2z(e1p + k1, v1);

        // ---- term set 1: A = side, k-step kp ----
        {
            float l00x, l00y, l01x, l01y, l10x, l10y, l11x, l11y;
            uint32_t a0 = pack_hi(s00.x, s00.y, l00x, l00y);
            uint32_t a1 = pack_hi(s10.x, s10.y, l10x, l10y);
            uint32_t a2 = pack_hi(s01.x, s01.y, l01x, l01y);
            uint32_t a3 = pack_hi(s11.x, s11.y, l11x, l11y);
            uint32_t q0 = pack_lo(l00x, l00y);
            uint32_t q1 = pack_lo(l10x, l10y);
            uint32_t q2 = pack_lo(l01x, l01y);
            uint32_t q3 = pack_lo(l11x, l11y);
            const int kb = kp * 32;
            #pragma unroll
            for (int nt = 0; nt < 8; ++nt) {
                uint32_t bh0 = *(const uint32_t*)(pb0 + nt * 8 * PITCH + kb);
                uint32_t bh1 = *(const uint32_t*)(pb0 + nt * 8 * PITCH + kb + 16);
                uint32_t bl0 = *(const uint32_t*)(pb1 + nt * 8 * PITCH + kb);
                uint32_t bl1 = *(const uint32_t*)(pb1 + nt * 8 * PITCH + kb + 16);
                mma_bf16(acc[nt], a0, a1, a2, a3, bh0, bh1);
                mma_bf16(acc[nt], q0, q1, q2, q3, bh0, bh1);
                mma_bf16(acc[nt], a0, a1, a2, a3, bl0, bl1);
            }
        }
        // ---- term set 2: A = side*emb, k-step kp+4 ----
        {
            float2 p00 = make_float2(s00.x * e00.x, s00.y * e00.y);
            float2 p01 = make_float2(s01.x * e01.x, s01.y * e01.y);
            float2 p10 = make_float2(s10.x * e10.x, s10.y * e10.y);
            float2 p11 = make_float2(s11.x * e11.x, s11.y * e11.y);
            float l00x, l00y, l01x, l01y, l10x, l10y, l11x, l11y;
            uint32_t a0 = pack_hi(p00.x, p00.y, l00x, l00y);
            uint32_t a1 = pack_hi(p10.x, p10.y, l10x, l10y);
            uint32_t a2 = pack_hi(p01.x, p01.y, l01x, l01y);
            uint32_t a3 = pack_hi(p11.x, p11.y, l11x, l11y);
            uint32_t q0 = pack_lo(l00x, l00y);
            uint32_t q1 = pack_lo(l10x, l10y);
            uint32_t q2 = pack_lo(l01x, l01y);
            uint32_t q3 = pack_lo(l11x, l11y);
            const int kb = (kp + 4) * 32;
            #pragma unroll
            for (int nt = 0; nt < 8; ++nt) {
                uint32_t bh0 = *(const uint32_t*)(pb0 + nt * 8 * PITCH + kb);
                uint32_t bh1 = *(const uint32_t*)(pb0 + nt * 8 * PITCH + kb + 16);
                uint32_t bl0 = *(const uint32_t*)(pb1 + nt * 8 * PITCH + kb);
                uint32_t bl1 = *(const uint32_t*)(pb1 + nt * 8 * PITCH + kb + 16);
                mma_bf16(acc[nt], a0, a1, a2, a3, bh0, bh1);
                mma_bf16(acc[nt], q0, q1, q2, q3, bh0, bh1);
                mma_bf16(acc[nt], a0, a1, a2, a3, bl0, bl1);
            }
        }
    }

    // --- epilogue: bias + leaky + row-L2; rows R0 and R1 ---
    float ssq0 = 0.f, ssq1 = 0.f;
    #pragma unroll
    for (int nt = 0; nt < 8; ++nt) {
        float2 bv = *(float2*)(sBias + nt * 8 + 2 * c4);
        float x0 = acc[nt][0] + bv.x, x1 = acc[nt][1] + bv.y;
        float y0 = acc[nt][2] + bv.x, y1 = acc[nt][3] + bv.y;
        x0 = (x0 > 0.f) ? x0 : 0.2f * x0;
        x1 = (x1 > 0.f) ? x1 : 0.2f * x1;
        y0 = (y0 > 0.f) ? y0 : 0.2f * y0;
        y1 = (y1 > 0.f) ? y1 : 0.2f * y1;
        acc[nt][0] = x0; acc[nt][1] = x1; acc[nt][2] = y0; acc[nt][3] = y1;
        ssq0 += x0 * x0 + x1 * x1;
        ssq1 += y0 * y0 + y1 * y1;
    }
    // reduce across the 4 lanes of the quad (same row)
    ssq0 += __shfl_xor_sync(0xffffffffu, ssq0, 1);
    ssq0 += __shfl_xor_sync(0xffffffffu, ssq0, 2);
    ssq1 += __shfl_xor_sync(0xffffffffu, ssq1, 1);
    ssq1 += __shfl_xor_sync(0xffffffffu, ssq1, 2);
    float sc0 = (ssq0 > 0.f) ? rsqrtf(ssq0) : 0.f;
    float sc1 = (ssq1 > 0.f) ? rsqrtf(ssq1) : 0.f;

    const int outc = (layer + 1) * 64;
    if (v0) {
        #pragma unroll
        for (int nt = 0; nt < 8; ++nt) {
            int col = nt * 8 + 2 * c4;
            *(float2*)(g_emb + (size_t)R0 * 64 + col) = make_float2(acc[nt][0], acc[nt][1]);
            *(float2*)(out + (size_t)R0 * 256 + outc + col) =
                make_float2(acc[nt][0] * sc0, acc[nt][1] * sc0);
        }
    }
    if (v1) {
        #pragma unroll
        for (int nt = 0; nt < 8; ++nt) {
            int col = nt * 8 + 2 * c4;
            *(float2*)(g_emb + (size_t)R1 * 64 + col) = make_float2(acc[nt][2], acc[nt][3]);
            *(float2*)(out + (size_t)R1 * 256 + outc + col) =
                make_float2(acc[nt][2] * sc1, acc[nt][3] * sc1);
        }
    }
}

// ---------------------------------------------------------------------------
// launch
// ---------------------------------------------------------------------------
extern "C" void kernel_launch(void* const* d_in, const int* in_sizes, int n_in,
                              void* d_out, int out_size) {
    const int*   rows = (const int*)d_in[0];
    const int*   cols = (const int*)d_in[1];
    const float* vals = (const float*)d_in[2];
    const float* ue   = (const float*)d_in[3];
    const float* ie   = (const float*)d_in[4];
    const float* Wc   = (const float*)d_in[5];
    const float* bc   = (const float*)d_in[6];
    const float* We   = (const float*)d_in[7];
    const float* be   = (const float*)d_in[8];
    float* out = (float*)d_out;

    cudaFuncSetAttribute(k_gemm, cudaFuncAttributeMaxDynamicSharedMemorySize, GEMM_SMEM);

    const int n_elem4 = N_NODES * 16;                 // 4.8M float4
    k_init<<<(n_elem4 + 255) / 256, 256>>>(ue, ie, out);
    k_prepB<<<96, 256>>>(Wc, We);

    // CSR build (per call; graph inputs are constant within a call)
    k_zcnt<<<NB_SCAN, 1024>>>();
    k_hist<<<(NNZ + 255) / 256, 256>>>(rows);
    k_scan1<<<NB_SCAN, 1024>>>();
    k_scan2<<<1, 512>>>();
    k_scan3<<<NB_SCAN, 1024>>>();
    k_scatter<<<(NNZ + 255) / 256, 256>>>(rows, cols, vals);

    const int spmm_blocks = (N_NODES + 15) / 16;      // 18750
    const int gemm_blocks = (N_NODES + 127) / 128;    // 2344

    for (int l = 0; l < 3; ++l) {
        k_spmm2<<<spmm_blocks, 256>>>();
        k_gemm<<<gemm_blocks, 256, GEMM_SMEM>>>(bc, be, out, l);
    }
}

// round 14
// speedup vs baseline: 2.0343x; 1.0565x over previous
#include <cuda_runtime.h>
#include <cuda_bf16.h>
#include <cstdint>

#define NUM_USERS 100000
#define NUM_ITEMS 200000
#define N_NODES   300000
#define NNZ       1200000
#define NB_SCAN   293                      // ceil(300000/1024)

// Scratch (allocation-free rule: __device__ globals)
__device__ float g_emb[N_NODES * 64];               // carried (UN-normalized) embeddings
__device__ float g_side[N_NODES * 64];              // SpMM output (fully overwritten per layer)
__device__ __nv_bfloat16 g_Bimg[3][2][64 * 128];    // [layer][hi/lo][n*128+k]
__device__ int  g_cnt[N_NODES];                     // histogram (zeroed by scan1 each call)
__device__ int  g_rowptr[N_NODES + 1];              // CSR row pointers
__device__ int  g_cur[N_NODES];                     // scatter cursors
__device__ int  g_blksum[NB_SCAN];                  // scan block sums
__device__ int2 g_edge[NNZ];                        // CSR edges: {col, val_bits}

// ---------------------------------------------------------------------------
// helpers
// ---------------------------------------------------------------------------
__device__ __forceinline__ void mma_bf16(float* d, uint32_t a0, uint32_t a1,
                                         uint32_t a2, uint32_t a3,
                                         uint32_t b0, uint32_t b1) {
    asm volatile("mma.sync.aligned.m16n8k16.row.col.f32.bf16.bf16.f32 "
                 "{%0,%1,%2,%3}, {%4,%5,%6,%7}, {%8,%9}, {%0,%1,%2,%3};"
                 : "+f"(d[0]), "+f"(d[1]), "+f"(d[2]), "+f"(d[3])
                 : "r"(a0), "r"(a1), "r"(a2), "r"(a3), "r"(b0), "r"(b1));
}
__device__ __forceinline__ uint32_t pack_hi(float a, float b, float& ra, float& rb) {
    __nv_bfloat16 ha = __float2bfloat16_rn(a), hb = __float2bfloat16_rn(b);
    ra = a - __bfloat162float(ha);
    rb = b - __bfloat162float(hb);
    return (uint32_t)__bfloat16_as_ushort(ha) | ((uint32_t)__bfloat16_as_ushort(hb) << 16);
}
__device__ __forceinline__ uint32_t pack_lo(float a, float b) {
    __nv_bfloat16 ha = __float2bfloat16_rn(a), hb = __float2bfloat16_rn(b);
    return (uint32_t)__bfloat16_as_ushort(ha) | ((uint32_t)__bfloat16_as_ushort(hb) << 16);
}
__device__ __forceinline__ float2 ldf2z(const float* p, bool v) {
    return v ? *(const float2*)p : make_float2(0.f, 0.f);
}

// ---------------------------------------------------------------------------
// init: g_emb = concat(user_emb, item_emb); out[:, 0:64] = g_emb
// ---------------------------------------------------------------------------
__global__ __launch_bounds__(256) void k_init(const float* __restrict__ ue,
                                              const float* __restrict__ ie,
                                              float* __restrict__ out) {
    int idx = blockIdx.x * 256 + threadIdx.x;      // [0, N_NODES*16)
    if (idx >= N_NODES * 16) return;
    int node = idx >> 4, q = idx & 15;
    float4 v;
    if (node < NUM_USERS)
        v = ((const float4*)ue)[node * 16 + q];
    else
        v = ((const float4*)ie)[(node - NUM_USERS) * 16 + q];
    ((float4*)g_emb)[idx] = v;
    ((float4*)out)[node * 64 + q] = v;
}

// ---------------------------------------------------------------------------
// precompute B images: B[k][n] = k<64 ? Wc[l][k][n] : We[l][k-64][n]
// stored transposed [n][k], split hi/lo bf16
// ---------------------------------------------------------------------------
__global__ __launch_bounds__(256) void k_prepB(const float* __restrict__ Wc,
                                               const float* __restrict__ We) {
    int idx = blockIdx.x * 256 + threadIdx.x;      // 3 * 8192
    if (idx >= 3 * 8192) return;
    int l = idx >> 13, r = idx & 8191, n = r >> 7, k = r & 127;
    float w = (k < 64) ? Wc[l * 4096 + k * 64 + n] : We[l * 4096 + (k - 64) * 64 + n];
    __nv_bfloat16 h = __float2bfloat16_rn(w);
    __nv_bfloat16 lo = __float2bfloat16_rn(w - __bfloat162float(h));
    g_Bimg[l][0][n * 128 + k] = h;
    g_Bimg[l][1][n * 128 + k] = lo;
}

// ---------------------------------------------------------------------------
// CSR build: histogram -> block scan -> scatter
// g_cnt is statically zero on call 1; scan1 re-zeroes it for the next call.
// ---------------------------------------------------------------------------
__global__ __launch_bounds__(256) void k_hist(const int* __restrict__ rows) {
    int e = blockIdx.x * 256 + threadIdx.x;
    if (e < NNZ) atomicAdd(&g_cnt[rows[e]], 1);
}
__global__ __launch_bounds__(1024) void k_scan1() {
    __shared__ int sm[1024];
    const int t = threadIdx.x, b = blockIdx.x;
    const int i = b * 1024 + t;
    int v = (i < N_NODES) ? g_cnt[i] : 0;
    if (i < N_NODES) g_cnt[i] = 0;                 // reset for next graph replay
    sm[t] = v;
    __syncthreads();
    #pragma unroll
    for (int off = 1; off < 1024; off <<= 1) {
        int x = (t >= off) ? sm[t - off] : 0;
        __syncthreads();
        sm[t] += x;
        __syncthreads();
    }
    if (i < N_NODES) g_rowptr[i] = sm[t] - v;      // exclusive within block
    if (t == 1023) g_blksum[b] = sm[1023];
}
__global__ __launch_bounds__(512) void k_scan2() {
    __shared__ int sm[512];
    const int t = threadIdx.x;
    int v = (t < NB_SCAN) ? g_blksum[t] : 0;
    sm[t] = v;
    __syncthreads();
    #pragma unroll
    for (int off = 1; off < 512; off <<= 1) {
        int x = (t >= off) ? sm[t - off] : 0;
        __syncthreads();
        sm[t] += x;
        __syncthreads();
    }
    if (t < NB_SCAN) g_blksum[t] = sm[t] - v;      // exclusive across blocks
    if (t == 0) g_rowptr[N_NODES] = NNZ;
}
__global__ __launch_bounds__(1024) void k_scan3() {
    int i = blockIdx.x * 1024 + threadIdx.x;
    if (i < N_NODES) {
        int rp = g_rowptr[i] + g_blksum[blockIdx.x];
        g_rowptr[i] = rp;
        g_cur[i] = rp;
    }
}
__global__ __launch_bounds__(256) void k_scatter(const int* __restrict__ rows,
                                                 const int* __restrict__ cols,
                                                 const float* __restrict__ vals) {
    int e = blockIdx.x * 256 + threadIdx.x;
    if (e >= NNZ) return;
    int pos = atomicAdd(&g_cur[rows[e]], 1);
    g_edge[pos] = make_int2(cols[e], __float_as_int(vals[e]));
}

// ---------------------------------------------------------------------------
// CSR SpMM v2: side[row] = sum_e val * emb[col].  Half-warp (16 lanes) per
// row, lane owns one float4 chunk. Predicated 4-wide edge batches: 4
// independent gathers in flight per iteration (MLP 4 instead of a serial
// edge->gather chain). OOB edges are {col 0, val 0} => contribute exactly 0.
// ---------------------------------------------------------------------------
__global__ __launch_bounds__(256) void k_spmm2() {
    const int tid = threadIdx.x, wid = tid >> 5, lane = tid & 31;
    const int half = lane >> 4, q = lane & 15;
    const int row = blockIdx.x * 16 + wid * 2 + half;
    if (row >= N_NODES) return;
    const int s = g_rowptr[row];
    const int len = g_rowptr[row + 1] - s;
    float4 acc = make_float4(0.f, 0.f, 0.f, 0.f);
    const float4* emb4 = (const float4*)g_emb;
    const int2 z2 = make_int2(0, 0);
    for (int b = 0; b < len; b += 4) {
        int2 e0 = (b + 0 < len) ? g_edge[s + b + 0] : z2;
        int2 e1 = (b + 1 < len) ? g_edge[s + b + 1] : z2;
        int2 e2 = (b + 2 < len) ? g_edge[s + b + 2] : z2;
        int2 e3 = (b + 3 < len) ? g_edge[s + b + 3] : z2;
        float4 x0 = emb4[(size_t)e0.x * 16 + q];
        float4 x1 = emb4[(size_t)e1.x * 16 + q];
        float4 x2 = emb4[(size_t)e2.x * 16 + q];
        float4 x3 = emb4[(size_t)e3.x * 16 + q];
        float v0 = __int_as_float(e0.y), v1 = __int_as_float(e1.y);
        float v2 = __int_as_float(e2.y), v3 = __int_as_float(e3.y);
        acc.x += v0 * x0.x + v1 * x1.x + v2 * x2.x + v3 * x3.x;
        acc.y += v0 * x0.y + v1 * x1.y + v2 * x2.y + v3 * x3.y;
        acc.z += v0 * x0.z + v1 * x1.z + v2 * x2.z + v3 * x3.z;
        acc.w += v0 * x0.w + v1 * x1.w + v2 * x2.w + v3 * x3.w;
    }
    ((float4*)g_side)[(size_t)row * 16 + q] = acc;
}

// ---------------------------------------------------------------------------
// HMMA fused layer, register-direct A, paired k-steps:
//   for kp in 0..3: load side+emb once; MMA set for A=side (k-step kp) and
//   A=side*emb (k-step kp+4). 3-term bf16 split. No side writes.
//   Epilogue: bias + leaky(0.2); g_emb <- act; out <- act/||act||.
// ---------------------------------------------------------------------------
#define PITCH 272                          // bytes per smem B row (136 bf16)
#define SB0   0                            // 64 rows -> 17408 B
#define SB1   17408
#define SBIAS 34816
#define GEMM_SMEM 35072

__global__ __launch_bounds__(256) void k_gemm(const float* __restrict__ bc,
                                              const float* __restrict__ be,
                                              float* __restrict__ out, int layer) {
    extern __shared__ char smem[];
    const int tid = threadIdx.x, wid = tid >> 5, lane = tid & 31;
    const int base = blockIdx.x * 128;
    float* sBias = (float*)(smem + SBIAS);

    // --- B operand: straight copy of precomputed hi/lo images, padded rows ---
    {
        const float4* bs = (const float4*)&g_Bimg[layer][0][0];   // 2048 float4 (hi then lo)
        #pragma unroll
        for (int it = 0; it < 8; ++it) {
            int i = it * 256 + tid;                // [0,2048)
            int img = i >> 10, r2 = i & 1023;
            int n = r2 >> 4, c = r2 & 15;
            *(float4*)(smem + (img ? SB1 : SB0) + n * PITCH + c * 16) = bs[i];
        }
    }
    if (tid < 64) sBias[tid] = bc[layer * 64 + tid] + be[layer * 64 + tid];
    __syncthreads();

    // --- mainloop: A fragments direct from global, B fragments from smem ---
    const int r = lane >> 2, c4 = lane & 3;
    const int R0 = base + 16 * wid + r;
    const int R1 = R0 + 8;
    const bool v0 = R0 < N_NODES, v1 = R1 < N_NODES;
    const float* s0p = g_side + (size_t)R0 * 64;
    const float* s1p = g_side + (size_t)R1 * 64;
    const float* e0p = g_emb + (size_t)R0 * 64;
    const float* e1p = g_emb + (size_t)R1 * 64;
    const int kA = 2 * c4, kB = 8 + 2 * c4;

    const char* pb0 = smem + SB0 + r * PITCH + c4 * 4;
    const char* pb1 = smem + SB1 + r * PITCH + c4 * 4;

    float acc[8][4];
    #pragma unroll
    for (int nt = 0; nt < 8; ++nt)
        #pragma unroll
        for (int i = 0; i < 4; ++i) acc[nt][i] = 0.f;

    #pragma unroll
    for (int kp = 0; kp < 4; ++kp) {
        const int k0 = kp * 16 + kA, k1 = kp * 16 + kB;
        float2 s00 = ldf2z(s0p + k0, v0), s01 = ldf2z(s0p + k1, v0);
        float2 s10 = ldf2z(s1p + k0, v1), s11 = ldf2z(s1p + k1, v1);
        float2 e00 = ldf2z(e0p + k0, v0), e01 = ldf2z(e0p + k1, v0);
        float2 e10 = ldf2z(e1p + k0, v1), e11 = ldf2z(e1p + k1, v1);

        // ---- term set 1: A = side, k-step kp ----
        {
            float l00x, l00y, l01x, l01y, l10x, l10y, l11x, l11y;
            uint32_t a0 = pack_hi(s00.x, s00.y, l00x, l00y);
            uint32_t a1 = pack_hi(s10.x, s10.y, l10x, l10y);
            uint32_t a2 = pack_hi(s01.x, s01.y, l01x, l01y);
            uint32_t a3 = pack_hi(s11.x, s11.y, l11x, l11y);
            uint32_t q0 = pack_lo(l00x, l00y);
            uint32_t q1 = pack_lo(l10x, l10y);
            uint32_t q2 = pack_lo(l01x, l01y);
            uint32_t q3 = pack_lo(l11x, l11y);
            const int kb = kp * 32;
            #pragma unroll
            for (int nt = 0; nt < 8; ++nt) {
                uint32_t bh0 = *(const uint32_t*)(pb0 + nt * 8 * PITCH + kb);
                uint32_t bh1 = *(const uint32_t*)(pb0 + nt * 8 * PITCH + kb + 16);
                uint32_t bl0 = *(const uint32_t*)(pb1 + nt * 8 * PITCH + kb);
                uint32_t bl1 = *(const uint32_t*)(pb1 + nt * 8 * PITCH + kb + 16);
                mma_bf16(acc[nt], a0, a1, a2, a3, bh0, bh1);
                mma_bf16(acc[nt], q0, q1, q2, q3, bh0, bh1);
                mma_bf16(acc[nt], a0, a1, a2, a3, bl0, bl1);
            }
        }
        // ---- term set 2: A = side*emb, k-step kp+4 ----
        {
            float2 p00 = make_float2(s00.x * e00.x, s00.y * e00.y);
            float2 p01 = make_float2(s01.x * e01.x, s01.y * e01.y);
            float2 p10 = make_float2(s10.x * e10.x, s10.y * e10.y);
            float2 p11 = make_float2(s11.x * e11.x, s11.y * e11.y);
            float l00x, l00y, l01x, l01y, l10x, l10y, l11x, l11y;
            uint32_t a0 = pack_hi(p00.x, p00.y, l00x, l00y);
            uint32_t a1 = pack_hi(p10.x, p10.y, l10x, l10y);
            uint32_t a2 = pack_hi(p01.x, p01.y, l01x, l01y);
            uint32_t a3 = pack_hi(p11.x, p11.y, l11x, l11y);
            uint32_t q0 = pack_lo(l00x, l00y);
            uint32_t q1 = pack_lo(l10x, l10y);
            uint32_t q2 = pack_lo(l01x, l01y);
            uint32_t q3 = pack_lo(l11x, l11y);
            const int kb = (kp + 4) * 32;
            #pragma unroll
            for (int nt = 0; nt < 8; ++nt) {
                uint32_t bh0 = *(const uint32_t*)(pb0 + nt * 8 * PITCH + kb);
                uint32_t bh1 = *(const uint32_t*)(pb0 + nt * 8 * PITCH + kb + 16);
                uint32_t bl0 = *(const uint32_t*)(pb1 + nt * 8 * PITCH + kb);
                uint32_t bl1 = *(const uint32_t*)(pb1 + nt * 8 * PITCH + kb + 16);
                mma_bf16(acc[nt], a0, a1, a2, a3, bh0, bh1);
                mma_bf16(acc[nt], q0, q1, q2, q3, bh0, bh1);
                mma_bf16(acc[nt], a0, a1, a2, a3, bl0, bl1);
            }
        }
    }

    // --- epilogue: bias + leaky + row-L2; rows R0 and R1 ---
    float ssq0 = 0.f, ssq1 = 0.f;
    #pragma unroll
    for (int nt = 0; nt < 8; ++nt) {
        float2 bv = *(float2*)(sBias + nt * 8 + 2 * c4);
        float x0 = acc[nt][0] + bv.x, x1 = acc[nt][1] + bv.y;
        float y0 = acc[nt][2] + bv.x, y1 = acc[nt][3] + bv.y;
        x0 = (x0 > 0.f) ? x0 : 0.2f * x0;
        x1 = (x1 > 0.f) ? x1 : 0.2f * x1;
        y0 = (y0 > 0.f) ? y0 : 0.2f * y0;
        y1 = (y1 > 0.f) ? y1 : 0.2f * y1;
        acc[nt][0] = x0; acc[nt][1] = x1; acc[nt][2] = y0; acc[nt][3] = y1;
        ssq0 += x0 * x0 + x1 * x1;
        ssq1 += y0 * y0 + y1 * y1;
    }
    // reduce across the 4 lanes of the quad (same row)
    ssq0 += __shfl_xor_sync(0xffffffffu, ssq0, 1);
    ssq0 += __shfl_xor_sync(0xffffffffu, ssq0, 2);
    ssq1 += __shfl_xor_sync(0xffffffffu, ssq1, 1);
    ssq1 += __shfl_xor_sync(0xffffffffu, ssq1, 2);
    float sc0 = (ssq0 > 0.f) ? rsqrtf(ssq0) : 0.f;
    float sc1 = (ssq1 > 0.f) ? rsqrtf(ssq1) : 0.f;

    const int outc = (layer + 1) * 64;
    if (v0) {
        #pragma unroll
        for (int nt = 0; nt < 8; ++nt) {
            int col = nt * 8 + 2 * c4;
            *(float2*)(g_emb + (size_t)R0 * 64 + col) = make_float2(acc[nt][0], acc[nt][1]);
            *(float2*)(out + (size_t)R0 * 256 + outc + col) =
                make_float2(acc[nt][0] * sc0, acc[nt][1] * sc0);
        }
    }
    if (v1) {
        #pragma unroll
        for (int nt = 0; nt < 8; ++nt) {
            int col = nt * 8 + 2 * c4;
            *(float2*)(g_emb + (size_t)R1 * 64 + col) = make_float2(acc[nt][2], acc[nt][3]);
            *(float2*)(out + (size_t)R1 * 256 + outc + col) =
                make_float2(acc[nt][2] * sc1, acc[nt][3] * sc1);
        }
    }
}

// ---------------------------------------------------------------------------
// launch
// ---------------------------------------------------------------------------
extern "C" void kernel_launch(void* const* d_in, const int* in_sizes, int n_in,
                              void* d_out, int out_size) {
    const int*   rows = (const int*)d_in[0];
    const int*   cols = (const int*)d_in[1];
    const float* vals = (const float*)d_in[2];
    const float* ue   = (const float*)d_in[3];
    const float* ie   = (const float*)d_in[4];
    const float* Wc   = (const float*)d_in[5];
    const float* bc   = (const float*)d_in[6];
    const float* We   = (const float*)d_in[7];
    const float* be   = (const float*)d_in[8];
    float* out = (float*)d_out;

    cudaFuncSetAttribute(k_gemm, cudaFuncAttributeMaxDynamicSharedMemorySize, GEMM_SMEM);

    const int n_elem4 = N_NODES * 16;                 // 4.8M float4
    k_init<<<(n_elem4 + 255) / 256, 256>>>(ue, ie, out);
    k_prepB<<<96, 256>>>(Wc, We);

    // CSR build (per call; g_cnt is zero on entry: static init on call 1,
    // re-zeroed by k_scan1 on every call thereafter)
    k_hist<<<(NNZ + 255) / 256, 256>>>(rows);
    k_scan1<<<NB_SCAN, 1024>>>();
    k_scan2<<<1, 512>>>();
    k_scan3<<<NB_SCAN, 1024>>>();
    k_scatter<<<(NNZ + 255) / 256, 256>>>(rows, cols, vals);

    const int spmm_blocks = (N_NODES + 15) / 16;      // 18750
    const int gemm_blocks = (N_NODES + 127) / 128;    // 2344

    for (int l = 0; l < 3; ++l) {
        k_spmm2<<<spmm_blocks, 256>>>();
        k_gemm<<<gemm_blocks, 256, GEMM_SMEM>>>(bc, be, out, l);
    }
}